// round 1
// baseline (speedup 1.0000x reference)
#include <cuda_runtime.h>
#include <cuda_fp16.h>
#include <cstdint>

#define E_ 8
#define T_ 4096
#define D_ 1024
#define F_ 4096
#define CAP 4096
#define NSLOT (E_*CAP)

// ---------------- static scratch (no allocations allowed) ----------------
__device__ __align__(16) __half g_w1h[(size_t)E_*D_*2*F_];   // 134 MB, gate/up interleaved
__device__ __align__(16) __half g_w2h[(size_t)E_*F_*D_];     // 67 MB
__device__ __align__(16) __half g_xg [(size_t)NSLOT*D_];     // 64 MB gathered x (fp16)
__device__ __align__(16) __half g_act[(size_t)NSLOT*F_];     // 268 MB intermediate act
__device__ int   g_cnt[E_];
__device__ int   g_tok[NSLOT];
__device__ float g_coef[NSLOT];
__device__ int   g_slot[2*T_];

// ---------------- small helpers ----------------
__device__ __forceinline__ unsigned smem_u32(const void* p){
    return (unsigned)__cvta_generic_to_shared(p);
}
__device__ __forceinline__ void cp16(void* s, const void* g){
    asm volatile("cp.async.cg.shared.global [%0], [%1], 16;\n" :: "r"(smem_u32(s)), "l"(g));
}
__device__ __forceinline__ void cp_commit(){ asm volatile("cp.async.commit_group;\n"); }
__device__ __forceinline__ void cp_wait0(){ asm volatile("cp.async.wait_group 0;\n"); }

__device__ __forceinline__ void ldsm4(unsigned&r0,unsigned&r1,unsigned&r2,unsigned&r3,unsigned a){
    asm volatile("ldmatrix.sync.aligned.m8n8.x4.shared.b16 {%0,%1,%2,%3}, [%4];\n"
        : "=r"(r0),"=r"(r1),"=r"(r2),"=r"(r3) : "r"(a));
}
__device__ __forceinline__ void ldsm4t(unsigned&r0,unsigned&r1,unsigned&r2,unsigned&r3,unsigned a){
    asm volatile("ldmatrix.sync.aligned.m8n8.x4.trans.shared.b16 {%0,%1,%2,%3}, [%4];\n"
        : "=r"(r0),"=r"(r1),"=r"(r2),"=r"(r3) : "r"(a));
}
__device__ __forceinline__ void mma16816(float* c, unsigned a0,unsigned a1,unsigned a2,unsigned a3,
                                         unsigned b0,unsigned b1){
    asm volatile("mma.sync.aligned.m16n8k16.row.col.f32.f16.f16.f32 "
        "{%0,%1,%2,%3},{%4,%5,%6,%7},{%8,%9},{%0,%1,%2,%3};\n"
        : "+f"(c[0]),"+f"(c[1]),"+f"(c[2]),"+f"(c[3])
        : "r"(a0),"r"(a1),"r"(a2),"r"(a3),"r"(b0),"r"(b1));
}

// ---------------- kernel 0: zero output + counts ----------------
__global__ void k_zero(float* __restrict__ out){
    int i = blockIdx.x*blockDim.x + threadIdx.x;
    float4 z = {0.f,0.f,0.f,0.f};
    ((float4*)out)[i] = z;
    if (blockIdx.x == 0 && threadIdx.x < E_) g_cnt[threadIdx.x] = 0;
}

// ---------------- kernel 1: routing (softmax top-2, renormalized) ----------------
__global__ void k_route(const float* __restrict__ gate){
    int t = blockIdx.x*blockDim.x + threadIdx.x;
    if (t >= T_) return;
    float g[E_];
    #pragma unroll
    for (int i=0;i<E_;i++) g[i] = gate[t*E_+i];
    int i1 = 0; float m1 = g[0];
    #pragma unroll
    for (int i=1;i<E_;i++) if (g[i] > m1){ m1 = g[i]; i1 = i; }
    int i2 = -1; float m2 = -1e30f;
    #pragma unroll
    for (int i=0;i<E_;i++){ if (i==i1) continue; if (g[i] > m2){ m2 = g[i]; i2 = i; } }
    float e2 = expf(m2 - m1);
    float w1 = 1.0f/(1.0f + e2);
    float w2 = e2*w1;
    int p1 = atomicAdd(&g_cnt[i1], 1);
    int s1 = i1*CAP + p1;
    g_tok[s1] = t; g_coef[s1] = w1; g_slot[2*t] = s1;
    int p2 = atomicAdd(&g_cnt[i2], 1);
    int s2 = i2*CAP + p2;
    g_tok[s2] = t; g_coef[s2] = w2; g_slot[2*t+1] = s2;
}

// ---------------- kernel 2: gather x rows (fp32 -> fp16) ----------------
__global__ void k_gather(const float* __restrict__ x){
    int p = blockIdx.x;            // pair index 0..8191
    int t = p >> 1;
    int slot = g_slot[p];
    const float4* src = (const float4*)(x + (size_t)t*D_);
    __half2* dst = (__half2*)(g_xg + (size_t)slot*D_);
    int tid = threadIdx.x;         // 128 threads, 8 floats each
    float4 a = src[tid*2], b = src[tid*2+1];
    dst[tid*4+0] = __floats2half2_rn(a.x, a.y);
    dst[tid*4+1] = __floats2half2_rn(a.z, a.w);
    dst[tid*4+2] = __floats2half2_rn(b.x, b.y);
    dst[tid*4+3] = __floats2half2_rn(b.z, b.w);
}

// ---------------- kernel 3: zero pad rows up to 128-multiple ----------------
__global__ void k_pad(){
    int e = blockIdx.x;
    int cnt = g_cnt[e];
    int end = (cnt + 127) & ~127;
    int n2 = (end - cnt)*D_/2;
    __half2* p = (__half2*)(g_xg + ((size_t)e*CAP + cnt)*D_);
    __half2 z = __float2half2_rn(0.f);
    for (int i = threadIdx.x; i < n2; i += blockDim.x) p[i] = z;
}

// ---------------- kernel 4: dequant w1 (interleave gate/up columns) ----------------
// w1h[e][k][2j+u] = (w1_q[e][k][j + u*F] - 8) * w1_scale[e][k/128][j + u*F]
__global__ void k_dq1(const int* __restrict__ q, const float* __restrict__ s){
    size_t gid = (size_t)blockIdx.x*blockDim.x + threadIdx.x;  // 8388608
    int c8 = (int)(gid & 1023);
    size_t kl = gid >> 10;                 // e*1024 + k
    int k = (int)(kl & 1023); int e = (int)(kl >> 10);
    int j0 = c8*4;
    const int4 gq = *(const int4*)(q + kl*8192 + j0);
    const int4 uq = *(const int4*)(q + kl*8192 + 4096 + j0);
    size_t sb = ((size_t)e*8 + (k>>7))*8192;
    const float4 sg = *(const float4*)(s + sb + j0);
    const float4 su = *(const float4*)(s + sb + 4096 + j0);
    __half2 o[4];
    o[0] = __floats2half2_rn((gq.x-8)*sg.x, (uq.x-8)*su.x);
    o[1] = __floats2half2_rn((gq.y-8)*sg.y, (uq.y-8)*su.y);
    o[2] = __floats2half2_rn((gq.z-8)*sg.z, (uq.z-8)*su.z);
    o[3] = __floats2half2_rn((gq.w-8)*sg.w, (uq.w-8)*su.w);
    *(uint4*)(g_w1h + kl*8192 + (size_t)c8*8) = *(uint4*)o;
}

// ---------------- kernel 5: dequant w2 ----------------
__global__ void k_dq2(const int* __restrict__ q, const float* __restrict__ s){
    size_t gid = (size_t)blockIdx.x*blockDim.x + threadIdx.x;  // 4194304
    int n8 = (int)(gid & 127);
    size_t kl = gid >> 7;                  // e*4096 + k
    int k = (int)(kl & 4095); int e = (int)(kl >> 12);
    int n0 = n8*8;
    const int4 qa = *(const int4*)(q + kl*1024 + n0);
    const int4 qb = *(const int4*)(q + kl*1024 + n0 + 4);
    size_t sbase = ((size_t)e*32 + (k>>7))*1024;
    const float4 sa = *(const float4*)(s + sbase + n0);
    const float4 sb = *(const float4*)(s + sbase + n0 + 4);
    __half2 o[4];
    o[0] = __floats2half2_rn((qa.x-8)*sa.x, (qa.y-8)*sa.y);
    o[1] = __floats2half2_rn((qa.z-8)*sa.z, (qa.w-8)*sa.w);
    o[2] = __floats2half2_rn((qb.x-8)*sb.x, (qb.y-8)*sb.y);
    o[3] = __floats2half2_rn((qb.z-8)*sb.z, (qb.w-8)*sb.w);
    *(uint4*)(g_w2h + kl*1024 + n0) = *(uint4*)o;
}

// ---------------- grouped GEMM (PHASE 1: x@w1 + silu*up -> act; PHASE 2: act@w2 -> out) ----------------
template<int PHASE>
__global__ __launch_bounds__(256,2) void k_gemm(float* __restrict__ out){
    constexpr int KDIM = (PHASE==1) ? 1024 : 4096;
    const int e  = blockIdx.x >> 5;
    const int mt = blockIdx.x & 31;
    const int cnt = g_cnt[e];
    const int mstart = mt*128;
    if (mstart >= cnt) return;
    const int rowbase = e*CAP + mstart;

    __shared__ __align__(16) __half As[2][128][40];
    __shared__ __align__(16) __half Bs[2][32][136];

    const int tid = threadIdx.x;
    const int lane = tid & 31, warp = tid >> 5;
    const int wm = warp & 3, wn = warp >> 2;

    const __half* Aptr;
    const __half* Bptr;
    size_t Bstride;
    if (PHASE==1){
        Aptr = g_xg + (size_t)rowbase*KDIM;
        Bptr = g_w1h + (size_t)e*D_*8192 + (size_t)blockIdx.y*128;   // interleaved cols
        Bstride = 8192;
    } else {
        Aptr = g_act + (size_t)rowbase*KDIM;
        Bptr = g_w2h + (size_t)e*F_*1024 + (size_t)blockIdx.y*128;
        Bstride = 1024;
    }

    auto loadA = [&](int st, int k0){
        #pragma unroll
        for (int it=0; it<2; it++){
            int idx = it*256 + tid;
            int r = idx >> 2, kc = (idx & 3) << 3;
            cp16(&As[st][r][kc], Aptr + (size_t)r*KDIM + k0 + kc);
        }
    };
    auto loadB = [&](int st, int k0){
        #pragma unroll
        for (int it=0; it<2; it++){
            int idx = it*256 + tid;
            int kr = idx >> 4, c = (idx & 15) << 3;
            cp16(&Bs[st][kr][c], Bptr + (size_t)(k0+kr)*Bstride + c);
        }
    };

    float acc[2][8][4];
    #pragma unroll
    for (int mi=0;mi<2;mi++)
        #pragma unroll
        for (int nj=0;nj<8;nj++)
            #pragma unroll
            for (int v=0;v<4;v++) acc[mi][nj][v] = 0.f;

    loadA(0,0); loadB(0,0); cp_commit();

    constexpr int NK = KDIM/32;
    #pragma unroll 1
    for (int kt=0; kt<NK; kt++){
        cp_wait0(); __syncthreads();
        int cur = kt & 1;
        if (kt+1 < NK){ loadA(cur^1,(kt+1)*32); loadB(cur^1,(kt+1)*32); cp_commit(); }
        #pragma unroll
        for (int kk=0; kk<2; kk++){
            int k0 = kk*16;
            unsigned a[2][4];
            #pragma unroll
            for (int mi=0;mi<2;mi++){
                int row = wm*32 + mi*16 + (lane & 15);
                int col = k0 + ((lane >> 4) << 3);
                ldsm4(a[mi][0],a[mi][1],a[mi][2],a[mi][3], smem_u32(&As[cur][row][col]));
            }
            unsigned b[8][2];
            #pragma unroll
            for (int nq=0;nq<4;nq++){
                int nb = wn*64 + nq*16;
                int lr = k0 + (((lane>>4)&1)<<3) + (lane & 7);
                int lc = nb + (((lane>>3)&1)<<3);
                unsigned r0,r1,r2,r3;
                ldsm4t(r0,r1,r2,r3, smem_u32(&Bs[cur][lr][lc]));
                b[2*nq  ][0]=r0; b[2*nq  ][1]=r2;
                b[2*nq+1][0]=r1; b[2*nq+1][1]=r3;
            }
            #pragma unroll
            for (int mi=0;mi<2;mi++)
                #pragma unroll
                for (int nj=0;nj<8;nj++)
                    mma16816(acc[mi][nj], a[mi][0],a[mi][1],a[mi][2],a[mi][3], b[nj][0],b[nj][1]);
        }
    }
    __syncthreads();

    if (PHASE==1){
        // fused SiLU(gate)*up: adjacent interleaved columns live in the same thread
        __half* stage = &As[0][0][0];   // 128 x 72 halves (fits in As)
        #pragma unroll
        for (int mi=0;mi<2;mi++){
            #pragma unroll
            for (int nj=0;nj<8;nj++){
                int r0 = wm*32 + mi*16 + (lane>>2);
                int c  = wn*32 + nj*4 + (lane&3);
                float g0=acc[mi][nj][0], u0=acc[mi][nj][1];
                float g1=acc[mi][nj][2], u1=acc[mi][nj][3];
                float a0 = g0/(1.f+expf(-g0))*u0;
                float a1 = g1/(1.f+expf(-g1))*u1;
                stage[r0*72 + c]     = __float2half(a0);
                stage[(r0+8)*72 + c] = __float2half(a1);
            }
        }
        __syncthreads();
        __half* dst = g_act + (size_t)rowbase*F_ + (size_t)blockIdx.y*64;
        #pragma unroll
        for (int it=0; it<4; it++){
            int idx = it*256 + tid;
            int r = idx >> 3, cc = (idx & 7) << 3;
            *(uint4*)(dst + (size_t)r*F_ + cc) = *(uint4*)(stage + r*72 + cc);
        }
    } else {
        #pragma unroll
        for (int mi=0;mi<2;mi++){
            #pragma unroll
            for (int h=0;h<2;h++){
                int r = wm*32 + mi*16 + (lane>>2) + h*8;
                int srow = mstart + r;
                if (srow >= cnt) continue;
                int slot = e*CAP + srow;
                int tok = g_tok[slot];
                float cf = g_coef[slot];
                float* op = out + (size_t)tok*D_ + (size_t)blockIdx.y*128;
                #pragma unroll
                for (int nj=0;nj<8;nj++){
                    int c = wn*64 + nj*8 + ((lane&3)<<1);
                    atomicAdd(op + c,     cf*acc[mi][nj][h*2+0]);
                    atomicAdd(op + c + 1, cf*acc[mi][nj][h*2+1]);
                }
            }
        }
    }
}

// ---------------- launch ----------------
extern "C" void kernel_launch(void* const* d_in, const int* in_sizes, int n_in,
                              void* d_out, int out_size){
    const float* x      = (const float*)d_in[0];
    const float* gating = (const float*)d_in[1];
    const int*   w1q    = (const int*)d_in[2];
    const int*   w2q    = (const int*)d_in[3];
    const float* w1s    = (const float*)d_in[4];
    const float* w2s    = (const float*)d_in[5];
    float* out = (float*)d_out;

    k_zero  <<<4096, 256>>>(out);
    k_route <<<16,   256>>>(gating);
    k_gather<<<8192, 128>>>(x);
    k_pad   <<<8,    256>>>();
    k_dq1   <<<32768,256>>>(w1q, w1s);
    k_dq2   <<<16384,256>>>(w2q, w2s);
    k_gemm<1><<<dim3(256,64),256>>>(out);
    k_gemm<2><<<dim3(256, 8),256>>>(out);
}

// round 3
// speedup vs baseline: 1.2735x; 1.2735x over previous
#include <cuda_runtime.h>
#include <cuda_fp16.h>
#include <cstdint>

#define E_ 8
#define T_ 4096
#define D_ 1024
#define F_ 4096
#define CAP 2048
#define NSLOT (E_*CAP)
#define MT_ 16

#define BM 128
#define BN 128
#define BK 64
#define STAGES 3
#define STAGE_BYTES 32768
#define SMEM_BYTES (STAGES*STAGE_BYTES + 128)

// ---------------- static scratch ----------------
__device__ __align__(16) __half g_w1h[(size_t)E_*D_*2*F_];   // [e][k][2j+u] gate/up interleaved
__device__ __align__(16) __half g_w2h[(size_t)E_*F_*D_];     // [e][k][n]
__device__ __align__(16) __half g_xg [(size_t)NSLOT*D_];     // gathered x (fp16)
__device__ __align__(16) __half g_act[(size_t)NSLOT*F_];     // intermediate act
__device__ int   g_cnt[E_];
__device__ int   g_tok[NSLOT];
__device__ float g_coef[NSLOT];
__device__ int   g_slot[2*T_];

// ---------------- helpers ----------------
__device__ __forceinline__ unsigned smem_u32(const void* p){
    return (unsigned)__cvta_generic_to_shared(p);
}
__device__ __forceinline__ void cp16s(unsigned s, const void* g){
    asm volatile("cp.async.cg.shared.global [%0], [%1], 16;\n" :: "r"(s), "l"(g));
}
__device__ __forceinline__ void cp_commit(){ asm volatile("cp.async.commit_group;\n"); }

__device__ __forceinline__ void ldsm4(unsigned&r0,unsigned&r1,unsigned&r2,unsigned&r3,unsigned a){
    asm volatile("ldmatrix.sync.aligned.m8n8.x4.shared.b16 {%0,%1,%2,%3}, [%4];\n"
        : "=r"(r0),"=r"(r1),"=r"(r2),"=r"(r3) : "r"(a));
}
__device__ __forceinline__ void ldsm4t(unsigned&r0,unsigned&r1,unsigned&r2,unsigned&r3,unsigned a){
    asm volatile("ldmatrix.sync.aligned.m8n8.x4.trans.shared.b16 {%0,%1,%2,%3}, [%4];\n"
        : "=r"(r0),"=r"(r1),"=r"(r2),"=r"(r3) : "r"(a));
}
__device__ __forceinline__ void mma16816(float* c, unsigned a0,unsigned a1,unsigned a2,unsigned a3,
                                         unsigned b0,unsigned b1){
    asm volatile("mma.sync.aligned.m16n8k16.row.col.f32.f16.f16.f32 "
        "{%0,%1,%2,%3},{%4,%5,%6,%7},{%8,%9},{%0,%1,%2,%3};\n"
        : "+f"(c[0]),"+f"(c[1]),"+f"(c[2]),"+f"(c[3])
        : "r"(a0),"r"(a1),"r"(a2),"r"(a3),"r"(b0),"r"(b1));
}

// swizzled smem offsets (conflict-free for cp.async 16B stores and ldmatrix)
// A tile: 128 rows x 64 halves (128B row, 8 chunks of 16B)
__device__ __forceinline__ unsigned swA(int r, int c){   // c in [0,8)
    return (unsigned)(r*128 + ((c ^ (r & 7)) << 4));
}
// B tile: 64 rows x 128 halves (256B row, 16 chunks of 16B, two 128B atoms)
__device__ __forceinline__ unsigned swB(int r, int c){   // c in [0,16)
    return (unsigned)(r*256 + ((c >> 3) << 7) + (((c & 7) ^ (r & 7)) << 4));
}

// ---------------- kernel 0: zero output + counts ----------------
__global__ void k_zero(float* __restrict__ out){
    int i = blockIdx.x*blockDim.x + threadIdx.x;
    float4 z = {0.f,0.f,0.f,0.f};
    ((float4*)out)[i] = z;
    if (blockIdx.x == 0 && threadIdx.x < E_) g_cnt[threadIdx.x] = 0;
}

// ---------------- kernel 1: routing (softmax top-2, renormalized) ----------------
__global__ void k_route(const float* __restrict__ gate){
    int t = blockIdx.x*blockDim.x + threadIdx.x;
    if (t >= T_) return;
    float g[E_];
    #pragma unroll
    for (int i=0;i<E_;i++) g[i] = gate[t*E_+i];
    int i1 = 0; float m1 = g[0];
    #pragma unroll
    for (int i=1;i<E_;i++) if (g[i] > m1){ m1 = g[i]; i1 = i; }
    int i2 = -1; float m2 = -1e30f;
    #pragma unroll
    for (int i=0;i<E_;i++){ if (i==i1) continue; if (g[i] > m2){ m2 = g[i]; i2 = i; } }
    float e2 = expf(m2 - m1);
    float w1 = 1.0f/(1.0f + e2);
    float w2 = e2*w1;
    int p1 = atomicAdd(&g_cnt[i1], 1);
    int s1 = i1*CAP + p1;
    g_tok[s1] = t; g_coef[s1] = w1; g_slot[2*t] = s1;
    int p2 = atomicAdd(&g_cnt[i2], 1);
    int s2 = i2*CAP + p2;
    g_tok[s2] = t; g_coef[s2] = w2; g_slot[2*t+1] = s2;
}

// ---------------- kernel 2: gather x rows (fp32 -> fp16) ----------------
__global__ void k_gather(const float* __restrict__ x){
    int p = blockIdx.x;
    int t = p >> 1;
    int slot = g_slot[p];
    const float4* src = (const float4*)(x + (size_t)t*D_);
    __half2* dst = (__half2*)(g_xg + (size_t)slot*D_);
    int tid = threadIdx.x;
    float4 a = src[tid*2], b = src[tid*2+1];
    dst[tid*4+0] = __floats2half2_rn(a.x, a.y);
    dst[tid*4+1] = __floats2half2_rn(a.z, a.w);
    dst[tid*4+2] = __floats2half2_rn(b.x, b.y);
    dst[tid*4+3] = __floats2half2_rn(b.z, b.w);
}

// ---------------- kernel 3: zero pad rows up to 128-multiple ----------------
__global__ void k_pad(){
    int e = blockIdx.x;
    int cnt = g_cnt[e];
    int end = (cnt + 127) & ~127;
    int n2 = (end - cnt)*D_/2;
    __half2* p = (__half2*)(g_xg + ((size_t)e*CAP + cnt)*D_);
    __half2 z = __float2half2_rn(0.f);
    for (int i = threadIdx.x; i < n2; i += blockDim.x) p[i] = z;
}

// ---------------- kernel 4: dequant w1 (interleave gate/up columns) ----------------
__global__ void k_dq1(const int* __restrict__ q, const float* __restrict__ s){
    size_t gid = (size_t)blockIdx.x*blockDim.x + threadIdx.x;  // 8388608
    int c8 = (int)(gid & 1023);
    size_t kl = gid >> 10;                 // e*1024 + k
    int k = (int)(kl & 1023); int e = (int)(kl >> 10);
    int j0 = c8*4;
    const int4 gq = *(const int4*)(q + kl*8192 + j0);
    const int4 uq = *(const int4*)(q + kl*8192 + 4096 + j0);
    size_t sb = ((size_t)e*8 + (k>>7))*8192;
    const float4 sg = *(const float4*)(s + sb + j0);
    const float4 su = *(const float4*)(s + sb + 4096 + j0);
    __half2 o[4];
    o[0] = __floats2half2_rn((gq.x-8)*sg.x, (uq.x-8)*su.x);
    o[1] = __floats2half2_rn((gq.y-8)*sg.y, (uq.y-8)*su.y);
    o[2] = __floats2half2_rn((gq.z-8)*sg.z, (uq.z-8)*su.z);
    o[3] = __floats2half2_rn((gq.w-8)*sg.w, (uq.w-8)*su.w);
    *(uint4*)(g_w1h + kl*8192 + (size_t)c8*8) = *(uint4*)o;
}

// ---------------- kernel 5: dequant w2 ----------------
__global__ void k_dq2(const int* __restrict__ q, const float* __restrict__ s){
    size_t gid = (size_t)blockIdx.x*blockDim.x + threadIdx.x;  // 4194304
    int n8 = (int)(gid & 127);
    size_t kl = gid >> 7;                  // e*4096 + k
    int k = (int)(kl & 4095); int e = (int)(kl >> 12);
    int n0 = n8*8;
    const int4 qa = *(const int4*)(q + kl*1024 + n0);
    const int4 qb = *(const int4*)(q + kl*1024 + n0 + 4);
    size_t sbase = ((size_t)e*32 + (k>>7))*1024;
    const float4 sa = *(const float4*)(s + sbase + n0);
    const float4 sb = *(const float4*)(s + sbase + n0 + 4);
    __half2 o[4];
    o[0] = __floats2half2_rn((qa.x-8)*sa.x, (qa.y-8)*sa.y);
    o[1] = __floats2half2_rn((qa.z-8)*sa.z, (qa.w-8)*sa.w);
    o[2] = __floats2half2_rn((qb.x-8)*sb.x, (qb.y-8)*sb.y);
    o[3] = __floats2half2_rn((qb.z-8)*sb.z, (qb.w-8)*sb.w);
    *(uint4*)(g_w2h + kl*1024 + n0) = *(uint4*)o;
}

// ---------------- grouped GEMM, 3-stage cp.async pipeline ----------------
// PHASE 1: act = silu(gate)*up from x@w1h ; PHASE 2: out += coef * act@w2h
template<int PHASE>
__global__ __launch_bounds__(256,2) void k_gemm(float* __restrict__ out){
    constexpr int KDIM = (PHASE==1) ? D_ : F_;
    constexpr int NT   = (PHASE==1) ? (2*F_/BN) : (D_/BN);
    constexpr int NK   = KDIM/BK;

    const int bx = blockIdx.x;
    const int mt = bx & (MT_-1);
    const int rest = bx >> 4;
    const int nt = rest % NT;
    const int e  = rest / NT;
    const int cnt = g_cnt[e];
    const int mstart = mt*BM;
    if (mstart >= cnt) return;
    const int rowbase = e*CAP + mstart;

    extern __shared__ __align__(128) char dsm[];
    char* sgen = dsm + ((128 - ((uintptr_t)dsm & 127)) & 127);
    const unsigned sbase = smem_u32(sgen);

    const int tid = threadIdx.x;
    const int lane = tid & 31, warp = tid >> 5;
    const int wm = warp & 3, wn = warp >> 2;

    const __half* Ap;
    const __half* Bp;
    size_t Bstride;
    if (PHASE==1){
        Ap = g_xg + (size_t)rowbase*KDIM;
        Bp = g_w1h + (size_t)e*D_*8192 + (size_t)nt*BN;
        Bstride = 8192;
    } else {
        Ap = g_act + (size_t)rowbase*KDIM;
        Bp = g_w2h + (size_t)e*F_*1024 + (size_t)nt*BN;
        Bstride = 1024;
    }

    auto ld_stage = [&](int st, int k0){
        unsigned a0 = sbase + st*STAGE_BYTES;
        unsigned b0 = a0 + 16384;
        #pragma unroll
        for (int it=0; it<4; it++){          // A: 128 x 64 halves
            int idx = it*256 + tid;
            int r = idx >> 3, u = idx & 7;
            cp16s(a0 + swA(r,u), Ap + (size_t)r*KDIM + k0 + u*8);
        }
        #pragma unroll
        for (int it=0; it<4; it++){          // B: 64 x 128 halves
            int idx = it*256 + tid;
            int kr = idx >> 4, c = idx & 15;
            cp16s(b0 + swB(kr,c), Bp + (size_t)(k0+kr)*Bstride + c*8);
        }
    };

    float acc[2][8][4];
    #pragma unroll
    for (int mi=0;mi<2;mi++)
        #pragma unroll
        for (int nj=0;nj<8;nj++)
            #pragma unroll
            for (int v=0;v<4;v++) acc[mi][nj][v] = 0.f;

    ld_stage(0, 0);  cp_commit();
    ld_stage(1, BK); cp_commit();

    #pragma unroll 1
    for (int kt=0; kt<NK; kt++){
        asm volatile("cp.async.wait_group 1;\n");
        __syncthreads();
        if (kt+2 < NK) ld_stage((kt+2)%STAGES, (kt+2)*BK);
        cp_commit();

        const int cur = kt % STAGES;
        const unsigned aS = sbase + cur*STAGE_BYTES;
        const unsigned bS = aS + 16384;

        #pragma unroll
        for (int kk=0; kk<4; kk++){
            const int k0h = kk*16;
            unsigned a[2][4];
            #pragma unroll
            for (int mi=0;mi<2;mi++){
                int row = wm*32 + mi*16 + (lane & 15);
                int chunk = kk*2 + (lane >> 4);
                ldsm4(a[mi][0],a[mi][1],a[mi][2],a[mi][3], aS + swA(row, chunk));
            }
            unsigned b[8][2];
            #pragma unroll
            for (int nq=0;nq<4;nq++){
                int nb = wn*64 + nq*16;
                int lr = k0h + (((lane>>4)&1)<<3) + (lane & 7);
                int lc = nb + (((lane>>3)&1)<<3);
                unsigned r0,r1,r2,r3;
                ldsm4t(r0,r1,r2,r3, bS + swB(lr, lc>>3));
                b[2*nq  ][0]=r0; b[2*nq  ][1]=r2;
                b[2*nq+1][0]=r1; b[2*nq+1][1]=r3;
            }
            #pragma unroll
            for (int mi=0;mi<2;mi++)
                #pragma unroll
                for (int nj=0;nj<8;nj++)
                    mma16816(acc[mi][nj], a[mi][0],a[mi][1],a[mi][2],a[mi][3], b[nj][0],b[nj][1]);
        }
    }
    __syncthreads();

    if (PHASE==1){
        // fused SiLU(gate)*up: interleaved column pairs live in the same thread
        __half* stage = (__half*)sgen;       // 128 x 72 halves
        #pragma unroll
        for (int mi=0;mi<2;mi++){
            #pragma unroll
            for (int nj=0;nj<8;nj++){
                int r0 = wm*32 + mi*16 + (lane>>2);
                int c  = wn*32 + nj*4 + (lane&3);
                float g0=acc[mi][nj][0], u0=acc[mi][nj][1];
                float g1=acc[mi][nj][2], u1=acc[mi][nj][3];
                float a0 = g0/(1.f+__expf(-g0))*u0;
                float a1 = g1/(1.f+__expf(-g1))*u1;
                stage[r0*72 + c]     = __float2half(a0);
                stage[(r0+8)*72 + c] = __float2half(a1);
            }
        }
        __syncthreads();
        __half* dst = g_act + (size_t)rowbase*F_ + (size_t)nt*64;
        #pragma unroll
        for (int it=0; it<4; it++){
            int idx = it*256 + tid;
            int r = idx >> 3, cc = (idx & 7) << 3;
            *(uint4*)(dst + (size_t)r*F_ + cc) = *(uint4*)(stage + r*72 + cc);
        }
    } else {
        #pragma unroll
        for (int mi=0;mi<2;mi++){
            #pragma unroll
            for (int h=0;h<2;h++){
                int r = wm*32 + mi*16 + (lane>>2) + h*8;
                int srow = mstart + r;
                if (srow >= cnt) continue;
                int slot = e*CAP + srow;
                int tok = g_tok[slot];
                float cf = g_coef[slot];
                float* op = out + (size_t)tok*D_ + (size_t)nt*BN;
                #pragma unroll
                for (int nj=0;nj<8;nj++){
                    int c = wn*64 + nj*8 + ((lane&3)<<1);
                    atomicAdd(op + c,     cf*acc[mi][nj][h*2+0]);
                    atomicAdd(op + c + 1, cf*acc[mi][nj][h*2+1]);
                }
            }
        }
    }
}

// ---------------- launch ----------------
extern "C" void kernel_launch(void* const* d_in, const int* in_sizes, int n_in,
                              void* d_out, int out_size){
    const float* x      = (const float*)d_in[0];
    const float* gating = (const float*)d_in[1];
    const int*   w1q    = (const int*)d_in[2];
    const int*   w2q    = (const int*)d_in[3];
    const float* w1s    = (const float*)d_in[4];
    const float* w2s    = (const float*)d_in[5];
    float* out = (float*)d_out;

    static bool attr_done = false;
    if (!attr_done){
        cudaFuncSetAttribute(k_gemm<1>, cudaFuncAttributeMaxDynamicSharedMemorySize, SMEM_BYTES);
        cudaFuncSetAttribute(k_gemm<2>, cudaFuncAttributeMaxDynamicSharedMemorySize, SMEM_BYTES);
        attr_done = true;
    }

    k_zero  <<<4096, 256>>>(out);
    k_route <<<16,   256>>>(gating);
    k_gather<<<8192, 128>>>(x);
    k_pad   <<<8,    256>>>();
    k_dq1   <<<32768,256>>>(w1q, w1s);
    k_dq2   <<<16384,256>>>(w2q, w2s);
    k_gemm<1><<<E_*(2*F_/BN)*MT_, 256, SMEM_BYTES>>>(out);
    k_gemm<2><<<E_*(D_/BN)*MT_,   256, SMEM_BYTES>>>(out);
}